// round 12
// baseline (speedup 1.0000x reference)
#include <cuda_runtime.h>
#include <cuda_bf16.h>
#include <math.h>
#include <stdint.h>

#define BB 8
#define CC 512
#define HH 32
#define WW 32
#define LL 1024   // H*W
#define NHD 8
#define HD 64
#define WHALF 16  // WINDOW/2

// ---------------- scratch (static device globals; no runtime allocation) ----
__device__ float g_xwalze[BB*CC*HH*WW];          // (B,C,H,W) post-walze
__device__ __nv_bfloat16 g_comb[BB*LL*2*CC];     // (B*L, 2C): [before | after]
__device__ float g_mask[BB*LL];                  // soft mask
__device__ __nv_bfloat16 g_qkv[BB*LL*3*CC];      // (B*L, 3C) bf16, Q pre-scaled
__device__ __nv_bfloat16 g_ctx[BB*LL*CC];        // attention context (bf16)
__device__ __nv_bfloat16 g_ipw[3*CC*CC];         // bf16 in_proj_w
__device__ __nv_bfloat16 g_opw[CC*CC];           // bf16 out_proj_w
__device__ __nv_bfloat16 g_w1[128*2*CC];         // bf16 det_w1

__device__ __forceinline__ float gelu_exact(float v) {
    return 0.5f * v * (1.0f + erff(v * 0.70710678118654752440f));
}
__device__ __forceinline__ uint32_t smem_u32(const void* p) {
    uint32_t a;
    asm("{ .reg .u64 t; cvta.to.shared.u64 t, %1; cvt.u32.u64 %0, t; }"
        : "=r"(a) : "l"(p));
    return a;
}
__device__ __forceinline__ void cp16(uint32_t dst, const void* src) {
    asm volatile("cp.async.cg.shared.global [%0], [%1], 16;" :: "r"(dst), "l"(src));
}
__device__ __forceinline__ void ldmx4(uint32_t addr, uint32_t& r0, uint32_t& r1,
                                      uint32_t& r2, uint32_t& r3) {
    asm volatile("ldmatrix.sync.aligned.m8n8.x4.shared.b16 {%0,%1,%2,%3}, [%4];"
                 : "=r"(r0), "=r"(r1), "=r"(r2), "=r"(r3) : "r"(addr));
}
__device__ __forceinline__ void ldmx2(uint32_t addr, uint32_t& r0, uint32_t& r1) {
    asm volatile("ldmatrix.sync.aligned.m8n8.x2.shared.b16 {%0,%1}, [%2];"
                 : "=r"(r0), "=r"(r1) : "r"(addr));
}
__device__ __forceinline__ void mma16(float* c, uint32_t a0, uint32_t a1,
                                      uint32_t a2, uint32_t a3,
                                      uint32_t b0, uint32_t b1) {
    asm volatile("mma.sync.aligned.m16n8k16.row.col.f32.bf16.bf16.f32 "
                 "{%0,%1,%2,%3}, {%4,%5,%6,%7}, {%8,%9}, {%0,%1,%2,%3};"
                 : "+f"(c[0]), "+f"(c[1]), "+f"(c[2]), "+f"(c[3])
                 : "r"(a0), "r"(a1), "r"(a2), "r"(a3), "r"(b0), "r"(b1));
}
__device__ __forceinline__ uint32_t bf2pack(float a, float b) {
    __nv_bfloat162 t = __floats2bfloat162_rn(a, b);
    return *(uint32_t*)&t;
}

// ====== bf16 mma.sync GEMM body (validated) =================================
// EPI: 0 = plain biased f32 store, 1 = bf16 store with Q-column 0.125 scaling,
//      2 = detector head, 3 = fused gated combine (smem-staged coalesced).
template<int EPI, int MT>
__device__ __forceinline__ void
gemm_body(int bm, int bn,
          const __nv_bfloat16* __restrict__ A, int lda,
          const __nv_bfloat16* __restrict__ Bm, int ldb,
          const float* __restrict__ bias,
          float* __restrict__ Cm, int ldc, int K,
          const float* __restrict__ aux1,   // EPI2: w2    EPI3: mask
          const float* __restrict__ aux2,   // EPI2: b2    EPI3: xwalze
          char* smem)
{
    constexpr int TM = MT * 32;
    constexpr int ABYTES = TM * 128;
    constexpr int BUFB = ABYTES + 16384;
    const uint32_t sb = smem_u32(smem);
    const int tid = threadIdx.x, lane = tid & 31, wid = tid >> 5;
    const int wm0 = (wid & 1) * (TM / 2), wn0 = (wid >> 1) * 32;

    const int ld_row = tid >> 3;
    const uint32_t st_off =
        (uint32_t)(ld_row * 128 + (((tid & 7) * 16) ^ ((ld_row & 7) << 4)));
    const __nv_bfloat16* Agb = A  + (size_t)(bm + ld_row) * lda + (tid & 7) * 8;
    const __nv_bfloat16* Bgb = Bm + (size_t)(bn + ld_row) * ldb + (tid & 7) * 8;

    auto load_tile = [&](int buf, int ch) {
        uint32_t da = sb + buf * BUFB + st_off;
        uint32_t db = da + ABYTES;
        const __nv_bfloat16* sa  = Agb + ch * 64;
        const __nv_bfloat16* sbp = Bgb + ch * 64;
#pragma unroll
        for (int p = 0; p < MT; p++)
            cp16(da + p * 4096, sa + (size_t)p * 32 * lda);
#pragma unroll
        for (int p = 0; p < 4; p++)
            cp16(db + p * 4096, sbp + (size_t)p * 32 * ldb);
        asm volatile("cp.async.commit_group;" ::: "memory");
    };

    const int arow  = wm0 + (lane & 15);
    const uint32_t akb = ((uint32_t)(lane >> 4)) << 4;
    const uint32_t aswz = (uint32_t)((arow & 7) << 4);
    const uint32_t a_rowbase = (uint32_t)(arow * 128);
    const int brow  = wn0 + ((lane >> 4) << 3) + (lane & 7);
    const uint32_t bkb = (uint32_t)(((lane >> 3) & 1) << 4);
    const uint32_t bswz = (uint32_t)((brow & 7) << 4);
    const uint32_t b_rowbase = (uint32_t)(ABYTES + brow * 128);

    float c[MT][4][4];
#pragma unroll
    for (int i = 0; i < MT; i++)
#pragma unroll
        for (int j = 0; j < 4; j++)
#pragma unroll
            for (int k = 0; k < 4; k++) c[i][j][k] = 0.0f;

    const int nch = K >> 6;
    load_tile(0, 0);
    load_tile(1, 1);

    for (int ch = 0; ch < nch; ch++) {
        const int buf = ch % 3;
        if (ch + 1 < nch) asm volatile("cp.async.wait_group 1;" ::: "memory");
        else              asm volatile("cp.async.wait_group 0;" ::: "memory");
        __syncthreads();
        if (ch + 2 < nch) load_tile((ch + 2) % 3, ch + 2);

        const uint32_t base = sb + buf * BUFB;
#pragma unroll
        for (int ks = 0; ks < 4; ks++) {
            const uint32_t kso = (uint32_t)(ks * 32);
            uint32_t a[MT][4];
#pragma unroll
            for (int mt = 0; mt < MT; mt++)
                ldmx4(base + a_rowbase + (uint32_t)(mt * 2048) + ((kso + akb) ^ aswz),
                      a[mt][0], a[mt][1], a[mt][2], a[mt][3]);
            uint32_t b[4][2];
#pragma unroll
            for (int nt2 = 0; nt2 < 2; nt2++)
                ldmx4(base + b_rowbase + (uint32_t)(nt2 * 2048) + ((kso + bkb) ^ bswz),
                      b[nt2*2][0], b[nt2*2][1], b[nt2*2+1][0], b[nt2*2+1][1]);
#pragma unroll
            for (int mt = 0; mt < MT; mt++)
#pragma unroll
                for (int nt = 0; nt < 4; nt++)
                    mma16(c[mt][nt], a[mt][0], a[mt][1], a[mt][2], a[mt][3],
                          b[nt][0], b[nt][1]);
        }
    }

    if (EPI == 1) {
        // bf16 store; Q columns (col < 512) pre-scaled by 1/sqrt(64)
        __nv_bfloat16* Cb = (__nv_bfloat16*)Cm;
#pragma unroll
        for (int mt = 0; mt < MT; mt++) {
            const int r0 = bm + wm0 + mt * 16 + (lane >> 2);
#pragma unroll
            for (int nt = 0; nt < 4; nt++) {
                const int col = bn + wn0 + nt * 8 + (lane & 3) * 2;
                float2 bs = *(const float2*)(bias + col);
                float sc = (col < 512) ? 0.125f : 1.0f;
                float v0 = (c[mt][nt][0] + bs.x) * sc;
                float v1 = (c[mt][nt][1] + bs.y) * sc;
                float v2 = (c[mt][nt][2] + bs.x) * sc;
                float v3 = (c[mt][nt][3] + bs.y) * sc;
                *(uint32_t*)(Cb + (size_t)r0 * ldc + col)       = bf2pack(v0, v1);
                *(uint32_t*)(Cb + (size_t)(r0 + 8) * ldc + col) = bf2pack(v2, v3);
            }
        }
        return;
    }

    if (EPI == 2) {
        float* red = (float*)smem;
        __syncthreads();
        if (tid < TM) red[tid] = 0.0f;
        __syncthreads();
#pragma unroll
        for (int mt = 0; mt < MT; mt++) {
            float pA = 0.0f, pB = 0.0f;
#pragma unroll
            for (int nt = 0; nt < 4; nt++) {
                int col = bn + wn0 + nt * 8 + (lane & 3) * 2;
                float2 bs = *(const float2*)(bias + col);
                float w0 = aux1[col], w1 = aux1[col + 1];
                pA += gelu_exact(c[mt][nt][0] + bs.x) * w0
                    + gelu_exact(c[mt][nt][1] + bs.y) * w1;
                pB += gelu_exact(c[mt][nt][2] + bs.x) * w0
                    + gelu_exact(c[mt][nt][3] + bs.y) * w1;
            }
            pA += __shfl_xor_sync(0xffffffffu, pA, 1);
            pA += __shfl_xor_sync(0xffffffffu, pA, 2);
            pB += __shfl_xor_sync(0xffffffffu, pB, 1);
            pB += __shfl_xor_sync(0xffffffffu, pB, 2);
            if ((lane & 3) == 0) {
                int rA = wm0 + mt * 16 + (lane >> 2);
                atomicAdd(&red[rA], pA);
                atomicAdd(&red[rA + 8], pB);
            }
        }
        __syncthreads();
        if (tid < TM)
            Cm[bm + tid] = 1.0f / (1.0f + __expf(-(red[tid] + aux2[0])));
        return;
    }

    if (EPI == 3) {
        // fused gated combine: stage c-major in smem, coalesced transposed store
        float* stage = (float*)smem;
        __syncthreads();
#pragma unroll
        for (int mt = 0; mt < MT; mt++) {
            const int row = wm0 + mt * 16 + (lane >> 2);
#pragma unroll
            for (int nt = 0; nt < 4; nt++) {
                const int col = wn0 + nt * 8 + (lane & 3) * 2;
                float2 bs = *(const float2*)(bias + bn + col);
                stage[col*136 + row]           = c[mt][nt][0] + bs.x;
                stage[(col+1)*136 + row]       = c[mt][nt][1] + bs.y;
                stage[col*136 + row + 8]       = c[mt][nt][2] + bs.x;
                stage[(col+1)*136 + row + 8]   = c[mt][nt][3] + bs.y;
            }
        }
        __syncthreads();
        const int bloc = bm >> 10, l0 = bm & (LL - 1);
        float4 mk = *(const float4*)(aux1 + bm + lane * 4);
#pragma unroll
        for (int cr = wid; cr < 128; cr += 8) {
            float4 vv = *(const float4*)&stage[cr*136 + lane*4];
            size_t o = ((size_t)(bloc*CC + bn + cr)) * LL + l0 + lane*4;
            float4 xw = *(const float4*)(aux2 + o);
            float4 r;
            r.x = xw.x + mk.x * vv.x;
            r.y = xw.y + mk.y * vv.y;
            r.z = xw.z + mk.z * vv.z;
            r.w = xw.w + mk.w * vv.w;
            *(float4*)(Cm + o) = r;
        }
        return;
    }

    // EPI == 0: plain biased f32 store
#pragma unroll
    for (int mt = 0; mt < MT; mt++) {
        const int r0 = bm + wm0 + mt * 16 + (lane >> 2);
#pragma unroll
        for (int nt = 0; nt < 4; nt++) {
            const int col = bn + wn0 + nt * 8 + (lane & 3) * 2;
            float2 bs = *(const float2*)(bias + col);
            float v0 = c[mt][nt][0] + bs.x, v1 = c[mt][nt][1] + bs.y;
            float v2 = c[mt][nt][2] + bs.x, v3 = c[mt][nt][3] + bs.y;
            *(float2*)(Cm + (size_t)r0 * ldc + col)       = make_float2(v0, v1);
            *(float2*)(Cm + (size_t)(r0 + 8) * ldc + col) = make_float2(v2, v3);
        }
    }
}

// ---- fused launch: QKV GEMM (1536 x 64-row CTAs) + detector (128 CTAs) -----
// MT=2 tiles + 3 CTAs/SM: 24 warps/SM to hide ldmatrix->mma latency.
#define QKV_BLOCKS 1536
#define FUSED_SMEM (3 * (64*128 + 16384))   // 73728
__global__ void __launch_bounds__(256, 3)
fused_qkv_det(const __nv_bfloat16* __restrict__ comb,
              const __nv_bfloat16* __restrict__ ipw,
              const float* __restrict__ ipb,
              __nv_bfloat16* __restrict__ qkv,
              const __nv_bfloat16* __restrict__ w1,
              const float* __restrict__ det_b1,
              const float* __restrict__ det_w2,
              const float* __restrict__ det_b2,
              float* __restrict__ mask)
{
    extern __shared__ char smem[];
    int bx = blockIdx.x;
    if (bx < QKV_BLOCKS) {
        int bn = (bx % 12) * 128;
        int bm = (bx / 12) * 64;
        gemm_body<1,2>(bm, bn, comb + CC, 2*CC, ipw, CC, ipb,
                       (float*)qkv, 3*CC, CC, nullptr, nullptr, smem);
    } else {
        int bm = (bx - QKV_BLOCKS) * 64;
        gemm_body<2,2>(bm, 0, comb, 2*CC, w1, 2*CC, det_b1,
                       mask, 1, 2*CC, det_w2, det_b2, smem);
    }
}

// ---- out_proj GEMM fused with gated residual combine ------------------------
__global__ void __launch_bounds__(256, 2)
outproj_combine(const __nv_bfloat16* __restrict__ ctx,
                const __nv_bfloat16* __restrict__ opw,
                const float* __restrict__ opb,
                float* __restrict__ out,
                const float* __restrict__ mask,
                const float* __restrict__ xwalze)
{
    extern __shared__ char smem[];
    gemm_body<3,4>(blockIdx.y * 128, blockIdx.x * 128, ctx, CC, opw, CC,
                   opb, out, 0, CC, mask, xwalze, smem);
}

// ---- walze (dwconv+BN+GELU) + weight rounding folded into one launch --------
#define WALZE_BLOCKS (BB*CC*HH*WW/256)           // 16384
#define RW_TOTAL (3*CC*CC + CC*CC + 128*2*CC)    // 1,179,648
#define RW_BLOCKS ((RW_TOTAL + 255)/256)         // 4608
__global__ void walze_rw(const float* __restrict__ x,
                         const float* __restrict__ dw_w,
                         const float* __restrict__ dw_b,
                         const float* __restrict__ sh_w,
                         const float* __restrict__ sh_b,
                         const float* __restrict__ mixw,
                         const float* __restrict__ gamma,
                         const float* __restrict__ beta,
                         const float* __restrict__ ipw,
                         const float* __restrict__ opw,
                         const float* __restrict__ w1)
{
    if (blockIdx.x >= WALZE_BLOCKS) {
        int i = (blockIdx.x - WALZE_BLOCKS) * 256 + threadIdx.x;
        const int N1 = 3*CC*CC, N2 = CC*CC, N3 = 128*2*CC;
        if (i < N1)                 g_ipw[i] = __float2bfloat16_rn(ipw[i]);
        else if (i < N1 + N2)       g_opw[i - N1] = __float2bfloat16_rn(opw[i - N1]);
        else if (i < N1 + N2 + N3)  g_w1[i - N1 - N2] = __float2bfloat16_rn(w1[i - N1 - N2]);
        return;
    }
    int idx = blockIdx.x * 256 + threadIdx.x;
    int w = idx & 31;
    int h = (idx >> 5) & 31;
    int c = (idx >> 10) & 511;
    int b = idx >> 19;

    const float* xb = x + ((size_t)(b*CC + c)) * (HH*WW);
    int hm = (h + HH - 1) & 31, hp = (h + 1) & 31;
    int wm = (w + WW - 1) & 31, wp = (w + 1) & 31;

    float v00 = xb[hm*WW+wm], v01 = xb[hm*WW+w], v02 = xb[hm*WW+wp];
    float v10 = xb[h *WW+wm], v11 = xb[h *WW+w], v12 = xb[h *WW+wp];
    float v20 = xb[hp*WW+wm], v21 = xb[hp*WW+w], v22 = xb[hp*WW+wp];

    const float* dk = dw_w + c*9;
    float main_out = v00*dk[0] + v01*dk[1] + v02*dk[2]
                   + v10*dk[3] + v11*dk[4] + v12*dk[5]
                   + v20*dk[6] + v21*dk[7] + v22*dk[8] + dw_b[c];
    float ex = v00*sh_w[0] + v01*sh_w[1] + v02*sh_w[2]
             + v10*sh_w[3] + v11*sh_w[4] + v12*sh_w[5]
             + v20*sh_w[6] + v21*sh_w[7] + v22*sh_w[8] + sh_b[0];

    float mix = 1.0f / (1.0f + __expf(-mixw[0]));
    float combined = mix * main_out + (1.0f - mix) * ex + v11;
    float bn = gamma[c] * combined * rsqrtf(1.0f + 1e-5f) + beta[c];
    g_xwalze[idx] = gelu_exact(bn);
}

// ---------------- pack: transpose x / x_walze into comb rows (bf16) ---------
__global__ void __launch_bounds__(256)
pack_kernel(const float* __restrict__ x)
{
    __shared__ float sx[32][33];
    __shared__ float sw[32][33];
    int bi = blockIdx.x;
    int lt = bi & 31, ct = (bi >> 5) & 15, b = bi >> 9;
    int c0 = ct * 32, l0 = lt * 32;
    int tx = threadIdx.x & 31, ty = threadIdx.x >> 5;
#pragma unroll
    for (int r = ty; r < 32; r += 8) {
        size_t src = (size_t)(b*CC + c0 + r) * LL + l0 + tx;
        sx[r][tx] = x[src];
        sw[r][tx] = g_xwalze[src];
    }
    __syncthreads();
#pragma unroll
    for (int r = ty; r < 32; r += 8) {
        size_t dst = (size_t)(b*LL + l0 + r) * (2*CC) + c0 + tx;
        g_comb[dst]      = __float2bfloat16_rn(sx[tx][r]);
        g_comb[dst + CC] = __float2bfloat16_rn(sw[tx][r]);
    }
}

// ============ banded attention via mma: S = QK^T, ctx = P V =================
#define ATT_VT  0                        // 64 x 208
#define ATT_LS  (ATT_VT + 64*208)        // 13312, 64 floats
#define ATT_Q   (ATT_LS + 256)           // 13568, 64 x 144
#define ATT_K   (ATT_Q + 64*144)         // 22784, 96 x 144
#define ATT_P   ATT_Q                    // aliases Q/K (needs 64*208 <= 23040)
#define ATT_SMEM (ATT_K + 96*144)        // 36608

__global__ void __launch_bounds__(256)
attn_kernel()
{
    extern __shared__ char smem[];
    const uint32_t sb = smem_u32(smem);
    int bi = blockIdx.x;
    int qt = bi & 15, h = (bi >> 4) & 7, b = bi >> 7;
    int q0 = qt * 64;
    int jlo = max(0, q0 - WHALF);
    int jhi = min(LL - 1, q0 + 63 + WHALF);
    int nrows = jhi - jlo + 1;              // 80 or 96
    int tid = threadIdx.x, lane = tid & 31, wid = tid >> 5;

    const __nv_bfloat16* qb = g_qkv + (size_t)(b*LL + q0) * (3*CC) + h*HD;
    for (int i = tid; i < 64*8; i += 256) {
        int r = i >> 3, cb = (i & 7) * 16;
        uint4 v = *(const uint4*)((const char*)(qb + (size_t)r * (3*CC)) + cb);
        *(uint4*)(smem + ATT_Q + r*144 + cb) = v;
    }
    const __nv_bfloat16* kb = g_qkv + (size_t)(b*LL + jlo) * (3*CC) + CC + h*HD;
    for (int i = tid; i < 96*8; i += 256) {
        int r = i >> 3, cb = (i & 7) * 16;
        uint4 v = make_uint4(0u, 0u, 0u, 0u);
        if (r < nrows)
            v = *(const uint4*)((const char*)(kb + (size_t)r * (3*CC)) + cb);
        *(uint4*)(smem + ATT_K + r*144 + cb) = v;
    }
    const __nv_bfloat16* vb = kb + CC;
    for (int i = tid; i < 96*16; i += 256) {
        int r = i >> 4, c4 = (i & 15) * 4;
        uint2 v = make_uint2(0u, 0u);
        if (r < nrows)
            v = *(const uint2*)(vb + (size_t)r * (3*CC) + c4);
        const __nv_bfloat16* hv = (const __nv_bfloat16*)&v;
        *(__nv_bfloat16*)(smem + ATT_VT + (c4+0)*208 + r*2) = hv[0];
        *(__nv_bfloat16*)(smem + ATT_VT + (c4+1)*208 + r*2) = hv[1];
        *(__nv_bfloat16*)(smem + ATT_VT + (c4+2)*208 + r*2) = hv[2];
        *(__nv_bfloat16*)(smem + ATT_VT + (c4+3)*208 + r*2) = hv[3];
    }
    if (tid < 64) ((float*)(smem + ATT_LS))[tid] = 0.0f;
    __syncthreads();

    const int wm0 = (wid & 1) * 32;
    const int wn0s = (wid >> 1) * 24;
    float s[2][3][4];
#pragma unroll
    for (int i = 0; i < 2; i++)
#pragma unroll
        for (int j = 0; j < 3; j++)
#pragma unroll
            for (int k = 0; k < 4; k++) s[i][j][k] = 0.0f;
    {
        const uint32_t aAddr = sb + ATT_Q + (uint32_t)((wm0 + (lane & 15)) * 144)
                             + ((uint32_t)(lane >> 4) << 4);
        const uint32_t bAddr4 = sb + ATT_K
                             + (uint32_t)((wn0s + ((lane >> 4) << 3) + (lane & 7)) * 144)
                             + (uint32_t)(((lane >> 3) & 1) << 4);
        const uint32_t bAddr2 = sb + ATT_K
                             + (uint32_t)((wn0s + 16 + (lane & 7)) * 144)
                             + (uint32_t)(((lane >> 3) & 1) << 4);
#pragma unroll
        for (int ks = 0; ks < 4; ks++) {
            const uint32_t kso = (uint32_t)(ks * 32);
            uint32_t a0[4], a1[4], bb[3][2];
            ldmx4(aAddr + kso,            a0[0], a0[1], a0[2], a0[3]);
            ldmx4(aAddr + 16*144 + kso,   a1[0], a1[1], a1[2], a1[3]);
            ldmx4(bAddr4 + kso, bb[0][0], bb[0][1], bb[1][0], bb[1][1]);
            ldmx2(bAddr2 + kso, bb[2][0], bb[2][1]);
#pragma unroll
            for (int nt = 0; nt < 3; nt++) {
                mma16(s[0][nt], a0[0], a0[1], a0[2], a0[3], bb[nt][0], bb[nt][1]);
                mma16(s[1][nt], a1[0], a1[1], a1[2], a1[3], bb[nt][0], bb[nt][1]);
            }
        }
    }
    __syncthreads();   // Q/K reads complete before P overwrites that region

    float* lsum = (float*)(smem + ATT_LS);
#pragma unroll
    for (int mt = 0; mt < 2; mt++) {
        int row = wm0 + mt * 16 + (lane >> 2);
        int qA = q0 + row, qB = qA + 8;
        float rs0 = 0.0f, rs1 = 0.0f;
#pragma unroll
        for (int nt = 0; nt < 3; nt++) {
            int col = wn0s + nt * 8 + (lane & 3) * 2;
            int gj0 = jlo + col, gj1 = gj0 + 1;
            bool a00 = (gj0 >= qA - WHALF) && (gj0 <= qA + WHALF) && (gj0 < LL);
            bool a01 = (gj1 >= qA - WHALF) && (gj1 <= qA + WHALF) && (gj1 < LL);
            bool a10 = (gj0 >= qB - WHALF) && (gj0 <= qB + WHALF) && (gj0 < LL);
            bool a11 = (gj1 >= qB - WHALF) && (gj1 <= qB + WHALF) && (gj1 < LL);
            float p00 = a00 ? __expf(s[mt][nt][0]) : 0.0f;
            float p01 = a01 ? __expf(s[mt][nt][1]) : 0.0f;
            float p10 = a10 ? __expf(s[mt][nt][2]) : 0.0f;
            float p11 = a11 ? __expf(s[mt][nt][3]) : 0.0f;
            rs0 += p00 + p01; rs1 += p10 + p11;
            *(uint32_t*)(smem + ATT_P + row*208 + col*2)     = bf2pack(p00, p01);
            *(uint32_t*)(smem + ATT_P + (row+8)*208 + col*2) = bf2pack(p10, p11);
        }
        rs0 += __shfl_xor_sync(0xffffffffu, rs0, 1);
        rs0 += __shfl_xor_sync(0xffffffffu, rs0, 2);
        rs1 += __shfl_xor_sync(0xffffffffu, rs1, 1);
        rs1 += __shfl_xor_sync(0xffffffffu, rs1, 2);
        if ((lane & 3) == 0) {
            atomicAdd(&lsum[row], rs0);
            atomicAdd(&lsum[row + 8], rs1);
        }
    }
    __syncthreads();

    const int wn0v = (wid >> 1) * 16;
    float o[2][2][4];
#pragma unroll
    for (int i = 0; i < 2; i++)
#pragma unroll
        for (int j = 0; j < 2; j++)
#pragma unroll
            for (int k = 0; k < 4; k++) o[i][j][k] = 0.0f;
    {
        const uint32_t aAddr = sb + ATT_P + (uint32_t)((wm0 + (lane & 15)) * 208)
                             + ((uint32_t)(lane >> 4) << 4);
        const uint32_t bAddr = sb + ATT_VT
                             + (uint32_t)((wn0v + ((lane >> 4) << 3) + (lane & 7)) * 208)
                             + (uint32_t)(((lane >> 3) & 1) << 4);
#pragma unroll
        for (int ks = 0; ks < 6; ks++) {
            const uint32_t kso = (uint32_t)(ks * 32);
            uint32_t a0[4], a1[4], bb[2][2];
            ldmx4(aAddr + kso,          a0[0], a0[1], a0[2], a0[3]);
            ldmx4(aAddr + 16*208 + kso, a1[0], a1[1], a1[2], a1[3]);
            ldmx4(bAddr + kso, bb[0][0], bb[0][1], bb[1][0], bb[1][1]);
#pragma unroll
            for (int nt = 0; nt < 2; nt++) {
                mma16(o[0][nt], a0[0], a0[1], a0[2], a0[3], bb[nt][0], bb[nt][1]);
                mma16(o[1][nt], a1[0], a1[1], a1[2], a1[3], bb[nt][0], bb[nt][1]);
            }
        }
    }

#pragma unroll
    for (int mt = 0; mt < 2; mt++) {
        int row = wm0 + mt * 16 + (lane >> 2);
        float inv0 = 1.0f / lsum[row];
        float inv1 = 1.0f / lsum[row + 8];
#pragma unroll
        for (int nt = 0; nt < 2; nt++) {
            int col = wn0v + nt * 8 + (lane & 3) * 2;
            __nv_bfloat16* d0 = g_ctx + (size_t)(b*LL + q0 + row) * CC + h*HD + col;
            __nv_bfloat16* d1 = d0 + (size_t)8 * CC;
            *(uint32_t*)d0 = bf2pack(o[mt][nt][0] * inv0, o[mt][nt][1] * inv0);
            *(uint32_t*)d1 = bf2pack(o[mt][nt][2] * inv1, o[mt][nt][3] * inv1);
        }
    }
}

// ---------------- host launcher ---------------------------------------------
extern "C" void kernel_launch(void* const* d_in, const int* in_sizes, int n_in,
                              void* d_out, int out_size)
{
    const float* x      = (const float*)d_in[0];
    const float* dw_w   = (const float*)d_in[1];
    const float* dw_b   = (const float*)d_in[2];
    const float* sh_w   = (const float*)d_in[3];
    const float* sh_b   = (const float*)d_in[4];
    const float* mixw   = (const float*)d_in[5];
    const float* gamma  = (const float*)d_in[6];
    const float* beta   = (const float*)d_in[7];
    const float* det_w1 = (const float*)d_in[8];
    const float* det_b1 = (const float*)d_in[9];
    const float* det_w2 = (const float*)d_in[10];
    const float* det_b2 = (const float*)d_in[11];
    const float* ipw    = (const float*)d_in[12];
    const float* ipb    = (const float*)d_in[13];
    const float* opw    = (const float*)d_in[14];
    const float* opb    = (const float*)d_in[15];
    float* out = (float*)d_out;

    __nv_bfloat16 *p_comb, *p_ctx, *p_ipw, *p_opw, *p_w1, *p_qkv;
    float *p_mask, *p_xwalze;
    cudaGetSymbolAddress((void**)&p_comb,    g_comb);
    cudaGetSymbolAddress((void**)&p_qkv,     g_qkv);
    cudaGetSymbolAddress((void**)&p_ctx,     g_ctx);
    cudaGetSymbolAddress((void**)&p_ipw,     g_ipw);
    cudaGetSymbolAddress((void**)&p_opw,     g_opw);
    cudaGetSymbolAddress((void**)&p_w1,      g_w1);
    cudaGetSymbolAddress((void**)&p_mask,    g_mask);
    cudaGetSymbolAddress((void**)&p_xwalze,  g_xwalze);

    const int SMEM128 = 3 * (128*128 + 16384);   // 98304 (outproj)
    cudaFuncSetAttribute((const void*)fused_qkv_det,
                         cudaFuncAttributeMaxDynamicSharedMemorySize, FUSED_SMEM);
    cudaFuncSetAttribute((const void*)outproj_combine,
                         cudaFuncAttributeMaxDynamicSharedMemorySize, SMEM128);
    cudaFuncSetAttribute((const void*)attn_kernel,
                         cudaFuncAttributeMaxDynamicSharedMemorySize, ATT_SMEM);

    // 1) walze (dwconv+BN+GELU) + bf16 weight rounding, one launch
    walze_rw<<<WALZE_BLOCKS + RW_BLOCKS, 256>>>(
        x, dw_w, dw_b, sh_w, sh_b, mixw, gamma, beta, ipw, opw, det_w1);

    // 2) pack: transpose into comb rows (bf16), fully coalesced
    pack_kernel<<<BB*16*32, 256>>>(x);

    // 3) fused QKV GEMM (64-row tiles, 3 CTAs/SM) + detector GEMM/head
    fused_qkv_det<<<QKV_BLOCKS + 128, 256, FUSED_SMEM>>>(
        p_comb, p_ipw, ipb, p_qkv, p_w1, det_b1, det_w2, det_b2, p_mask);

    // 4) banded attention (mma-based, bf16 I/O)
    attn_kernel<<<BB*NHD*(LL/64), 256, ATT_SMEM>>>();

    // 5) out_proj GEMM fused with gated residual combine -> out
    {
        dim3 g(CC/128, (BB*LL)/128);
        outproj_combine<<<g, 256, SMEM128>>>(p_ctx, p_opw, opb, out,
                                             p_mask, p_xwalze);
    }
}

// round 13
// speedup vs baseline: 1.0917x; 1.0917x over previous
#include <cuda_runtime.h>
#include <cuda_bf16.h>
#include <math.h>
#include <stdint.h>

#define BB 8
#define CC 512
#define HH 32
#define WW 32
#define LL 1024   // H*W
#define NHD 8
#define HD 64
#define WHALF 16  // WINDOW/2

// ---------------- scratch (static device globals; no runtime allocation) ----
__device__ float g_xwalze[BB*CC*HH*WW];          // (B,C,H,W) post-walze
__device__ __nv_bfloat16 g_comb[BB*LL*2*CC];     // (B*L, 2C): [before | after]
__device__ float g_mask[BB*LL];                  // soft mask
__device__ __nv_bfloat16 g_qkv[BB*LL*3*CC];      // (B*L, 3C) bf16, Q pre-scaled
__device__ __nv_bfloat16 g_ctx[BB*LL*CC];        // attention context (bf16)
__device__ __nv_bfloat16 g_ipw[3*CC*CC];         // bf16 in_proj_w
__device__ __nv_bfloat16 g_opw[CC*CC];           // bf16 out_proj_w
__device__ __nv_bfloat16 g_w1[128*2*CC];         // bf16 det_w1

__device__ __forceinline__ float gelu_exact(float v) {
    return 0.5f * v * (1.0f + erff(v * 0.70710678118654752440f));
}
__device__ __forceinline__ uint32_t smem_u32(const void* p) {
    uint32_t a;
    asm("{ .reg .u64 t; cvta.to.shared.u64 t, %1; cvt.u32.u64 %0, t; }"
        : "=r"(a) : "l"(p));
    return a;
}
__device__ __forceinline__ void cp16(uint32_t dst, const void* src) {
    asm volatile("cp.async.cg.shared.global [%0], [%1], 16;" :: "r"(dst), "l"(src));
}
__device__ __forceinline__ void ldmx4(uint32_t addr, uint32_t& r0, uint32_t& r1,
                                      uint32_t& r2, uint32_t& r3) {
    asm volatile("ldmatrix.sync.aligned.m8n8.x4.shared.b16 {%0,%1,%2,%3}, [%4];"
                 : "=r"(r0), "=r"(r1), "=r"(r2), "=r"(r3) : "r"(addr));
}
__device__ __forceinline__ void ldmx2(uint32_t addr, uint32_t& r0, uint32_t& r1) {
    asm volatile("ldmatrix.sync.aligned.m8n8.x2.shared.b16 {%0,%1}, [%2];"
                 : "=r"(r0), "=r"(r1) : "r"(addr));
}
__device__ __forceinline__ void mma16(float* c, uint32_t a0, uint32_t a1,
                                      uint32_t a2, uint32_t a3,
                                      uint32_t b0, uint32_t b1) {
    asm volatile("mma.sync.aligned.m16n8k16.row.col.f32.bf16.bf16.f32 "
                 "{%0,%1,%2,%3}, {%4,%5,%6,%7}, {%8,%9}, {%0,%1,%2,%3};"
                 : "+f"(c[0]), "+f"(c[1]), "+f"(c[2]), "+f"(c[3])
                 : "r"(a0), "r"(a1), "r"(a2), "r"(a3), "r"(b0), "r"(b1));
}
__device__ __forceinline__ uint32_t bf2pack(float a, float b) {
    __nv_bfloat162 t = __floats2bfloat162_rn(a, b);
    return *(uint32_t*)&t;
}

// ====== bf16 mma.sync GEMM body (validated) =================================
// EPI: 1 = bf16 store with Q-column 0.125 scaling, 2 = detector head,
//      3 = fused gated combine (smem-staged coalesced).
template<int EPI, int MT>
__device__ __forceinline__ void
gemm_body(int bm, int bn,
          const __nv_bfloat16* __restrict__ A, int lda,
          const __nv_bfloat16* __restrict__ Bm, int ldb,
          const float* __restrict__ bias,
          float* __restrict__ Cm, int ldc, int K,
          const float* __restrict__ aux1,   // EPI2: w2    EPI3: mask
          const float* __restrict__ aux2,   // EPI2: b2    EPI3: xwalze
          char* smem)
{
    constexpr int TM = MT * 32;
    constexpr int ABYTES = TM * 128;
    constexpr int BUFB = ABYTES + 16384;
    const uint32_t sb = smem_u32(smem);
    const int tid = threadIdx.x, lane = tid & 31, wid = tid >> 5;
    const int wm0 = (wid & 1) * (TM / 2), wn0 = (wid >> 1) * 32;

    const int ld_row = tid >> 3;
    const uint32_t st_off =
        (uint32_t)(ld_row * 128 + (((tid & 7) * 16) ^ ((ld_row & 7) << 4)));
    const __nv_bfloat16* Agb = A  + (size_t)(bm + ld_row) * lda + (tid & 7) * 8;
    const __nv_bfloat16* Bgb = Bm + (size_t)(bn + ld_row) * ldb + (tid & 7) * 8;

    auto load_tile = [&](int buf, int ch) {
        uint32_t da = sb + buf * BUFB + st_off;
        uint32_t db = da + ABYTES;
        const __nv_bfloat16* sa  = Agb + ch * 64;
        const __nv_bfloat16* sbp = Bgb + ch * 64;
#pragma unroll
        for (int p = 0; p < MT; p++)
            cp16(da + p * 4096, sa + (size_t)p * 32 * lda);
#pragma unroll
        for (int p = 0; p < 4; p++)
            cp16(db + p * 4096, sbp + (size_t)p * 32 * ldb);
        asm volatile("cp.async.commit_group;" ::: "memory");
    };

    const int arow  = wm0 + (lane & 15);
    const uint32_t akb = ((uint32_t)(lane >> 4)) << 4;
    const uint32_t aswz = (uint32_t)((arow & 7) << 4);
    const uint32_t a_rowbase = (uint32_t)(arow * 128);
    const int brow  = wn0 + ((lane >> 4) << 3) + (lane & 7);
    const uint32_t bkb = (uint32_t)(((lane >> 3) & 1) << 4);
    const uint32_t bswz = (uint32_t)((brow & 7) << 4);
    const uint32_t b_rowbase = (uint32_t)(ABYTES + brow * 128);

    float c[MT][4][4];
#pragma unroll
    for (int i = 0; i < MT; i++)
#pragma unroll
        for (int j = 0; j < 4; j++)
#pragma unroll
            for (int k = 0; k < 4; k++) c[i][j][k] = 0.0f;

    const int nch = K >> 6;
    load_tile(0, 0);
    load_tile(1, 1);

    for (int ch = 0; ch < nch; ch++) {
        const int buf = ch % 3;
        if (ch + 1 < nch) asm volatile("cp.async.wait_group 1;" ::: "memory");
        else              asm volatile("cp.async.wait_group 0;" ::: "memory");
        __syncthreads();
        if (ch + 2 < nch) load_tile((ch + 2) % 3, ch + 2);

        const uint32_t base = sb + buf * BUFB;
#pragma unroll
        for (int ks = 0; ks < 4; ks++) {
            const uint32_t kso = (uint32_t)(ks * 32);
            uint32_t a[MT][4];
#pragma unroll
            for (int mt = 0; mt < MT; mt++)
                ldmx4(base + a_rowbase + (uint32_t)(mt * 2048) + ((kso + akb) ^ aswz),
                      a[mt][0], a[mt][1], a[mt][2], a[mt][3]);
            uint32_t b[4][2];
#pragma unroll
            for (int nt2 = 0; nt2 < 2; nt2++)
                ldmx4(base + b_rowbase + (uint32_t)(nt2 * 2048) + ((kso + bkb) ^ bswz),
                      b[nt2*2][0], b[nt2*2][1], b[nt2*2+1][0], b[nt2*2+1][1]);
#pragma unroll
            for (int mt = 0; mt < MT; mt++)
#pragma unroll
                for (int nt = 0; nt < 4; nt++)
                    mma16(c[mt][nt], a[mt][0], a[mt][1], a[mt][2], a[mt][3],
                          b[nt][0], b[nt][1]);
        }
    }

    if (EPI == 1) {
        __nv_bfloat16* Cb = (__nv_bfloat16*)Cm;
#pragma unroll
        for (int mt = 0; mt < MT; mt++) {
            const int r0 = bm + wm0 + mt * 16 + (lane >> 2);
#pragma unroll
            for (int nt = 0; nt < 4; nt++) {
                const int col = bn + wn0 + nt * 8 + (lane & 3) * 2;
                float2 bs = *(const float2*)(bias + col);
                float sc = (col < 512) ? 0.125f : 1.0f;
                float v0 = (c[mt][nt][0] + bs.x) * sc;
                float v1 = (c[mt][nt][1] + bs.y) * sc;
                float v2 = (c[mt][nt][2] + bs.x) * sc;
                float v3 = (c[mt][nt][3] + bs.y) * sc;
                *(uint32_t*)(Cb + (size_t)r0 * ldc + col)       = bf2pack(v0, v1);
                *(uint32_t*)(Cb + (size_t)(r0 + 8) * ldc + col) = bf2pack(v2, v3);
            }
        }
        return;
    }

    if (EPI == 2) {
        float* red = (float*)smem;
        __syncthreads();
        if (tid < TM) red[tid] = 0.0f;
        __syncthreads();
#pragma unroll
        for (int mt = 0; mt < MT; mt++) {
            float pA = 0.0f, pB = 0.0f;
#pragma unroll
            for (int nt = 0; nt < 4; nt++) {
                int col = bn + wn0 + nt * 8 + (lane & 3) * 2;
                float2 bs = *(const float2*)(bias + col);
                float w0 = aux1[col], w1 = aux1[col + 1];
                pA += gelu_exact(c[mt][nt][0] + bs.x) * w0
                    + gelu_exact(c[mt][nt][1] + bs.y) * w1;
                pB += gelu_exact(c[mt][nt][2] + bs.x) * w0
                    + gelu_exact(c[mt][nt][3] + bs.y) * w1;
            }
            pA += __shfl_xor_sync(0xffffffffu, pA, 1);
            pA += __shfl_xor_sync(0xffffffffu, pA, 2);
            pB += __shfl_xor_sync(0xffffffffu, pB, 1);
            pB += __shfl_xor_sync(0xffffffffu, pB, 2);
            if ((lane & 3) == 0) {
                int rA = wm0 + mt * 16 + (lane >> 2);
                atomicAdd(&red[rA], pA);
                atomicAdd(&red[rA + 8], pB);
            }
        }
        __syncthreads();
        if (tid < TM)
            Cm[bm + tid] = 1.0f / (1.0f + __expf(-(red[tid] + aux2[0])));
        return;
    }

    if (EPI == 3) {
        float* stage = (float*)smem;
        __syncthreads();
#pragma unroll
        for (int mt = 0; mt < MT; mt++) {
            const int row = wm0 + mt * 16 + (lane >> 2);
#pragma unroll
            for (int nt = 0; nt < 4; nt++) {
                const int col = wn0 + nt * 8 + (lane & 3) * 2;
                float2 bs = *(const float2*)(bias + bn + col);
                stage[col*136 + row]           = c[mt][nt][0] + bs.x;
                stage[(col+1)*136 + row]       = c[mt][nt][1] + bs.y;
                stage[col*136 + row + 8]       = c[mt][nt][2] + bs.x;
                stage[(col+1)*136 + row + 8]   = c[mt][nt][3] + bs.y;
            }
        }
        __syncthreads();
        const int bloc = bm >> 10, l0 = bm & (LL - 1);
        float4 mk = *(const float4*)(aux1 + bm + lane * 4);
#pragma unroll
        for (int cr = wid; cr < 128; cr += 8) {
            float4 vv = *(const float4*)&stage[cr*136 + lane*4];
            size_t o = ((size_t)(bloc*CC + bn + cr)) * LL + l0 + lane*4;
            float4 xw = *(const float4*)(aux2 + o);
            float4 r;
            r.x = xw.x + mk.x * vv.x;
            r.y = xw.y + mk.y * vv.y;
            r.z = xw.z + mk.z * vv.z;
            r.w = xw.w + mk.w * vv.w;
            *(float4*)(Cm + o) = r;
        }
        return;
    }
}

// ---- fused launch: QKV GEMM (768 CTAs, MT=4) + detector (128 CTAs) ---------
// (reverted to R11 config — MT=2 split regressed in R12)
#define QKV_BLOCKS 768
#define FUSED_SMEM (3 * (128*128 + 16384))   // 98304
__global__ void __launch_bounds__(256, 2)
fused_qkv_det(const __nv_bfloat16* __restrict__ comb,
              const __nv_bfloat16* __restrict__ ipw,
              const float* __restrict__ ipb,
              __nv_bfloat16* __restrict__ qkv,
              const __nv_bfloat16* __restrict__ w1,
              const float* __restrict__ det_b1,
              const float* __restrict__ det_w2,
              const float* __restrict__ det_b2,
              float* __restrict__ mask)
{
    extern __shared__ char smem[];
    int bx = blockIdx.x;
    if (bx < QKV_BLOCKS) {
        int bn = (bx % 12) * 128;
        int bm = (bx / 12) * 128;
        gemm_body<1,4>(bm, bn, comb + CC, 2*CC, ipw, CC, ipb,
                       (float*)qkv, 3*CC, CC, nullptr, nullptr, smem);
    } else {
        int bm = (bx - QKV_BLOCKS) * 64;
        gemm_body<2,2>(bm, 0, comb, 2*CC, w1, 2*CC, det_b1,
                       mask, 1, 2*CC, det_w2, det_b2, smem);
    }
}

// ---- out_proj GEMM fused with gated residual combine ------------------------
__global__ void __launch_bounds__(256, 2)
outproj_combine(const __nv_bfloat16* __restrict__ ctx,
                const __nv_bfloat16* __restrict__ opw,
                const float* __restrict__ opb,
                float* __restrict__ out,
                const float* __restrict__ mask,
                const float* __restrict__ xwalze)
{
    extern __shared__ char smem[];
    gemm_body<3,4>(blockIdx.y * 128, blockIdx.x * 128, ctx, CC, opw, CC,
                   opb, out, 0, CC, mask, xwalze, smem);
}

// ==== fused walze: full-plane conv/BN/GELU + comb pack + xwalze, 1 launch ====
// Block (bi < 256) = (b, 16-channel tile): stages 16 x 1024 x-plane in smem,
// circular 3x3 conv needs zero re-reads. Writes comb (before/after, bf16)
// and g_xwalze (coalesced via slab transpose buffer).
// Tail blocks (bi >= 256) round the GEMM weights to bf16.
#define WCH 16
#define WPAD 1028                                  // padded floats per channel
#define WALZE_PLANES 256                            // 8 b x 32 ct
#define RW_TOTAL (3*CC*CC + CC*CC + 128*2*CC)       // 1,179,648
#define RW_BLOCKS ((RW_TOTAL + 255)/256)            // 4608
#define WALZE_SMEM ((WCH*WPAD + WCH*136) * 4)       // 74496 B

__global__ void __launch_bounds__(256)
walze_fused(const float* __restrict__ x,
            const float* __restrict__ dw_w,
            const float* __restrict__ dw_b,
            const float* __restrict__ sh_w,
            const float* __restrict__ sh_b,
            const float* __restrict__ mixw,
            const float* __restrict__ gamma,
            const float* __restrict__ beta,
            const float* __restrict__ ipw,
            const float* __restrict__ opw,
            const float* __restrict__ w1)
{
    int bi = blockIdx.x;
    int tid = threadIdx.x;
    if (bi >= WALZE_PLANES) {
        int i = (bi - WALZE_PLANES) * 256 + tid;
        const int N1 = 3*CC*CC, N2 = CC*CC, N3 = 128*2*CC;
        if (i < N1)                 g_ipw[i] = __float2bfloat16_rn(ipw[i]);
        else if (i < N1 + N2)       g_opw[i - N1] = __float2bfloat16_rn(opw[i - N1]);
        else if (i < N1 + N2 + N3)  g_w1[i - N1 - N2] = __float2bfloat16_rn(w1[i - N1 - N2]);
        return;
    }
    extern __shared__ float sx[];            // [WCH][WPAD]
    float* swo = sx + WCH * WPAD;            // [WCH][136]

    int ct = bi & 31, b = bi >> 5;
    int c0 = ct * WCH;

    // load 16 x 1024 plane, float4 coalesced
    for (int i = tid; i < WCH * 256; i += 256) {
        int c = i >> 8, l4 = (i & 255) * 4;
        float4 v = *(const float4*)(x + ((size_t)(b*CC + c0 + c)) * LL + l4);
        *(float4*)(sx + c * WPAD + l4) = v;
    }
    __syncthreads();

    const int c = tid & 15;
    const int lb = tid >> 4;                 // 0..15
    const float* dk = dw_w + (c0 + c) * 9;
    float d0 = dk[0], d1 = dk[1], d2 = dk[2], d3 = dk[3], d4 = dk[4],
          d5 = dk[5], d6 = dk[6], d7 = dk[7], d8 = dk[8];
    float dwb = dw_b[c0 + c];
    float gm = gamma[c0 + c] * rsqrtf(1.0f + 1e-5f);
    float bt = beta[c0 + c];
    float s0 = sh_w[0], s1 = sh_w[1], s2 = sh_w[2], s3 = sh_w[3], s4 = sh_w[4],
          s5 = sh_w[5], s6 = sh_w[6], s7 = sh_w[7], s8 = sh_w[8];
    float shb = sh_b[0];
    float mix = 1.0f / (1.0f + __expf(-mixw[0]));
    const float* row = sx + c * WPAD;

    for (int k = 0; k < 8; k++) {
#pragma unroll
        for (int j = 0; j < 8; j++) {
            int ll = lb + 16 * j;            // 0..127 within slab
            int l = k * 128 + ll;
            int h = l >> 5, w = l & 31;
            int hm = (h + 31) & 31, hp = (h + 1) & 31;
            int wm = (w + 31) & 31, wp = (w + 1) & 31;
            float v00 = row[hm*32+wm], v01 = row[hm*32+w], v02 = row[hm*32+wp];
            float v10 = row[h*32+wm],  v11 = row[h*32+w],  v12 = row[h*32+wp];
            float v20 = row[hp*32+wm], v21 = row[hp*32+w], v22 = row[hp*32+wp];
            float mo = v00*d0 + v01*d1 + v02*d2 + v10*d3 + v11*d4 + v12*d5
                     + v20*d6 + v21*d7 + v22*d8 + dwb;
            float ex = v00*s0 + v01*s1 + v02*s2 + v10*s3 + v11*s4 + v12*s5
                     + v20*s6 + v21*s7 + v22*s8 + shb;
            float xw = gelu_exact(gm * (mix*mo + (1.0f-mix)*ex + v11) + bt);
            size_t dst = ((size_t)(b*LL + l)) * (2*CC) + c0 + c;
            g_comb[dst]      = __float2bfloat16_rn(v11);
            g_comb[dst + CC] = __float2bfloat16_rn(xw);
            swo[c * 136 + ll] = xw;
        }
        __syncthreads();
        // coalesced xwalze store for this slab
#pragma unroll
        for (int j = 0; j < 8; j++) {
            int idx = tid + 256 * j;         // 0..2047
            int c2 = idx >> 7, l2 = idx & 127;
            g_xwalze[((size_t)(b*CC + c0 + c2)) * LL + k*128 + l2] =
                swo[c2 * 136 + l2];
        }
        __syncthreads();
    }
}

// ============ banded attention via mma: S = QK^T, ctx = P V =================
#define ATT_VT  0                        // 64 x 208
#define ATT_LS  (ATT_VT + 64*208)        // 13312, 64 floats
#define ATT_Q   (ATT_LS + 256)           // 13568, 64 x 144
#define ATT_K   (ATT_Q + 64*144)         // 22784, 96 x 144
#define ATT_P   ATT_Q                    // aliases Q/K (needs 64*208 <= 23040)
#define ATT_SMEM (ATT_K + 96*144)        // 36608

__global__ void __launch_bounds__(256)
attn_kernel()
{
    extern __shared__ char smem[];
    const uint32_t sb = smem_u32(smem);
    int bi = blockIdx.x;
    int qt = bi & 15, h = (bi >> 4) & 7, b = bi >> 7;
    int q0 = qt * 64;
    int jlo = max(0, q0 - WHALF);
    int jhi = min(LL - 1, q0 + 63 + WHALF);
    int nrows = jhi - jlo + 1;              // 80 or 96
    int tid = threadIdx.x, lane = tid & 31, wid = tid >> 5;

    const __nv_bfloat16* qb = g_qkv + (size_t)(b*LL + q0) * (3*CC) + h*HD;
    for (int i = tid; i < 64*8; i += 256) {
        int r = i >> 3, cb = (i & 7) * 16;
        uint4 v = *(const uint4*)((const char*)(qb + (size_t)r * (3*CC)) + cb);
        *(uint4*)(smem + ATT_Q + r*144 + cb) = v;
    }
    const __nv_bfloat16* kb = g_qkv + (size_t)(b*LL + jlo) * (3*CC) + CC + h*HD;
    for (int i = tid; i < 96*8; i += 256) {
        int r = i >> 3, cb = (i & 7) * 16;
        uint4 v = make_uint4(0u, 0u, 0u, 0u);
        if (r < nrows)
            v = *(const uint4*)((const char*)(kb + (size_t)r * (3*CC)) + cb);
        *(uint4*)(smem + ATT_K + r*144 + cb) = v;
    }
    const __nv_bfloat16* vb = kb + CC;
    for (int i = tid; i < 96*16; i += 256) {
        int r = i >> 4, c4 = (i & 15) * 4;
        uint2 v = make_uint2(0u, 0u);
        if (r < nrows)
            v = *(const uint2*)(vb + (size_t)r * (3*CC) + c4);
        const __nv_bfloat16* hv = (const __nv_bfloat16*)&v;
        *(__nv_bfloat16*)(smem + ATT_VT + (c4+0)*208 + r*2) = hv[0];
        *(__nv_bfloat16*)(smem + ATT_VT + (c4+1)*208 + r*2) = hv[1];
        *(__nv_bfloat16*)(smem + ATT_VT + (c4+2)*208 + r*2) = hv[2];
        *(__nv_bfloat16*)(smem + ATT_VT + (c4+3)*208 + r*2) = hv[3];
    }
    if (tid < 64) ((float*)(smem + ATT_LS))[tid] = 0.0f;
    __syncthreads();

    const int wm0 = (wid & 1) * 32;
    const int wn0s = (wid >> 1) * 24;
    float s[2][3][4];
#pragma unroll
    for (int i = 0; i < 2; i++)
#pragma unroll
        for (int j = 0; j < 3; j++)
#pragma unroll
            for (int k = 0; k < 4; k++) s[i][j][k] = 0.0f;
    {
        const uint32_t aAddr = sb + ATT_Q + (uint32_t)((wm0 + (lane & 15)) * 144)
                             + ((uint32_t)(lane >> 4) << 4);
        const uint32_t bAddr4 = sb + ATT_K
                             + (uint32_t)((wn0s + ((lane >> 4) << 3) + (lane & 7)) * 144)
                             + (uint32_t)(((lane >> 3) & 1) << 4);
        const uint32_t bAddr2 = sb + ATT_K
                             + (uint32_t)((wn0s + 16 + (lane & 7)) * 144)
                             + (uint32_t)(((lane >> 3) & 1) << 4);
#pragma unroll
        for (int ks = 0; ks < 4; ks++) {
            const uint32_t kso = (uint32_t)(ks * 32);
            uint32_t a0[4], a1[4], bb[3][2];
            ldmx4(aAddr + kso,            a0[0], a0[1], a0[2], a0[3]);
            ldmx4(aAddr + 16*144 + kso,   a1[0], a1[1], a1[2], a1[3]);
            ldmx4(bAddr4 + kso, bb[0][0], bb[0][1], bb[1][0], bb[1][1]);
            ldmx2(bAddr2 + kso, bb[2][0], bb[2][1]);
#pragma unroll
            for (int nt = 0; nt < 3; nt++) {
                mma16(s[0][nt], a0[0], a0[1], a0[2], a0[3], bb[nt][0], bb[nt][1]);
                mma16(s[1][nt], a1[0], a1[1], a1[2], a1[3], bb[nt][0], bb[nt][1]);
            }
        }
    }
    __syncthreads();   // Q/K reads complete before P overwrites that region

    float* lsum = (float*)(smem + ATT_LS);
#pragma unroll
    for (int mt = 0; mt < 2; mt++) {
        int row = wm0 + mt * 16 + (lane >> 2);
        int qA = q0 + row, qB = qA + 8;
        float rs0 = 0.0f, rs1 = 0.0f;
#pragma unroll
        for (int nt = 0; nt < 3; nt++) {
            int col = wn0s + nt * 8 + (lane & 3) * 2;
            int gj0 = jlo + col, gj1 = gj0 + 1;
            bool a00 = (gj0 >= qA - WHALF) && (gj0 <= qA + WHALF) && (gj0 < LL);
            bool a01 = (gj1 >= qA - WHALF) && (gj1 <= qA + WHALF) && (gj1 < LL);
            bool a10 = (gj0 >= qB - WHALF) && (gj0 <= qB + WHALF) && (gj0 < LL);
            bool a11 = (gj1 >= qB - WHALF) && (gj1 <= qB + WHALF) && (gj1 < LL);
            float p00 = a00 ? __expf(s[mt][nt][0]) : 0.0f;
            float p01 = a01 ? __expf(s[mt][nt][1]) : 0.0f;
            float p10 = a10 ? __expf(s[mt][nt][2]) : 0.0f;
            float p11 = a11 ? __expf(s[mt][nt][3]) : 0.0f;
            rs0 += p00 + p01; rs1 += p10 + p11;
            *(uint32_t*)(smem + ATT_P + row*208 + col*2)     = bf2pack(p00, p01);
            *(uint32_t*)(smem + ATT_P + (row+8)*208 + col*2) = bf2pack(p10, p11);
        }
        rs0 += __shfl_xor_sync(0xffffffffu, rs0, 1);
        rs0 += __shfl_xor_sync(0xffffffffu, rs0, 2);
        rs1 += __shfl_xor_sync(0xffffffffu, rs1, 1);
        rs1 += __shfl_xor_sync(0xffffffffu, rs1, 2);
        if ((lane & 3) == 0) {
            atomicAdd(&lsum[row], rs0);
            atomicAdd(&lsum[row + 8], rs1);
        }
    }
    __syncthreads();

    const int wn0v = (wid >> 1) * 16;
    float o[2][2][4];
#pragma unroll
    for (int i = 0; i < 2; i++)
#pragma unroll
        for (int j = 0; j < 2; j++)
#pragma unroll
            for (int k = 0; k < 4; k++) o[i][j][k] = 0.0f;
    {
        const uint32_t aAddr = sb + ATT_P + (uint32_t)((wm0 + (lane & 15)) * 208)
                             + ((uint32_t)(lane >> 4) << 4);
        const uint32_t bAddr = sb + ATT_VT
                             + (uint32_t)((wn0v + ((lane >> 4) << 3) + (lane & 7)) * 208)
                             + (uint32_t)(((lane >> 3) & 1) << 4);
#pragma unroll
        for (int ks = 0; ks < 6; ks++) {
            const uint32_t kso = (uint32_t)(ks * 32);
            uint32_t a0[4], a1[4], bb[2][2];
            ldmx4(aAddr + kso,          a0[0], a0[1], a0[2], a0[3]);
            ldmx4(aAddr + 16*208 + kso, a1[0], a1[1], a1[2], a1[3]);
            ldmx4(bAddr + kso, bb[0][0], bb[0][1], bb[1][0], bb[1][1]);
#pragma unroll
            for (int nt = 0; nt < 2; nt++) {
                mma16(o[0][nt], a0[0], a0[1], a0[2], a0[3], bb[nt][0], bb[nt][1]);
                mma16(o[1][nt], a1[0], a1[1], a1[2], a1[3], bb[nt][0], bb[nt][1]);
            }
        }
    }

#pragma unroll
    for (int mt = 0; mt < 2; mt++) {
        int row = wm0 + mt * 16 + (lane >> 2);
        float inv0 = 1.0f / lsum[row];
        float inv1 = 1.0f / lsum[row + 8];
#pragma unroll
        for (int nt = 0; nt < 2; nt++) {
            int col = wn0v + nt * 8 + (lane & 3) * 2;
            __nv_bfloat16* d0 = g_ctx + (size_t)(b*LL + q0 + row) * CC + h*HD + col;
            __nv_bfloat16* d1 = d0 + (size_t)8 * CC;
            *(uint32_t*)d0 = bf2pack(o[mt][nt][0] * inv0, o[mt][nt][1] * inv0);
            *(uint32_t*)d1 = bf2pack(o[mt][nt][2] * inv1, o[mt][nt][3] * inv1);
        }
    }
}

// ---------------- host launcher ---------------------------------------------
extern "C" void kernel_launch(void* const* d_in, const int* in_sizes, int n_in,
                              void* d_out, int out_size)
{
    const float* x      = (const float*)d_in[0];
    const float* dw_w   = (const float*)d_in[1];
    const float* dw_b   = (const float*)d_in[2];
    const float* sh_w   = (const float*)d_in[3];
    const float* sh_b   = (const float*)d_in[4];
    const float* mixw   = (const float*)d_in[5];
    const float* gamma  = (const float*)d_in[6];
    const float* beta   = (const float*)d_in[7];
    const float* det_w1 = (const float*)d_in[8];
    const float* det_b1 = (const float*)d_in[9];
    const float* det_w2 = (const float*)d_in[10];
    const float* det_b2 = (const float*)d_in[11];
    const float* ipw    = (const float*)d_in[12];
    const float* ipb    = (const float*)d_in[13];
    const float* opw    = (const float*)d_in[14];
    const float* opb    = (const float*)d_in[15];
    float* out = (float*)d_out;

    __nv_bfloat16 *p_comb, *p_ctx, *p_ipw, *p_opw, *p_w1, *p_qkv;
    float *p_mask, *p_xwalze;
    cudaGetSymbolAddress((void**)&p_comb,    g_comb);
    cudaGetSymbolAddress((void**)&p_qkv,     g_qkv);
    cudaGetSymbolAddress((void**)&p_ctx,     g_ctx);
    cudaGetSymbolAddress((void**)&p_ipw,     g_ipw);
    cudaGetSymbolAddress((void**)&p_opw,     g_opw);
    cudaGetSymbolAddress((void**)&p_w1,      g_w1);
    cudaGetSymbolAddress((void**)&p_mask,    g_mask);
    cudaGetSymbolAddress((void**)&p_xwalze,  g_xwalze);

    cudaFuncSetAttribute((const void*)fused_qkv_det,
                         cudaFuncAttributeMaxDynamicSharedMemorySize, FUSED_SMEM);
    cudaFuncSetAttribute((const void*)outproj_combine,
                         cudaFuncAttributeMaxDynamicSharedMemorySize, FUSED_SMEM);
    cudaFuncSetAttribute((const void*)attn_kernel,
                         cudaFuncAttributeMaxDynamicSharedMemorySize, ATT_SMEM);
    cudaFuncSetAttribute((const void*)walze_fused,
                         cudaFuncAttributeMaxDynamicSharedMemorySize, WALZE_SMEM);

    // 1) fused walze: conv/BN/GELU + comb pack + xwalze (+ weight rounding tail)
    walze_fused<<<WALZE_PLANES + RW_BLOCKS, 256, WALZE_SMEM>>>(
        x, dw_w, dw_b, sh_w, sh_b, mixw, gamma, beta, ipw, opw, det_w1);

    // 2) fused QKV GEMM (bf16 out, Q pre-scaled) + detector GEMM/head
    fused_qkv_det<<<QKV_BLOCKS + 128, 256, FUSED_SMEM>>>(
        p_comb, p_ipw, ipb, p_qkv, p_w1, det_b1, det_w2, det_b2, p_mask);

    // 3) banded attention (mma-based, bf16 I/O)
    attn_kernel<<<BB*NHD*(LL/64), 256, ATT_SMEM>>>();

    // 4) out_proj GEMM fused with gated residual combine -> out
    {
        dim3 g(CC/128, (BB*LL)/128);
        outproj_combine<<<g, 256, FUSED_SMEM>>>(p_ctx, p_opw, opb, out,
                                                p_mask, p_xwalze);
    }
}

// round 14
// speedup vs baseline: 1.1783x; 1.0794x over previous
#include <cuda_runtime.h>
#include <cuda_bf16.h>
#include <math.h>
#include <stdint.h>

#define BB 8
#define CC 512
#define HH 32
#define WW 32
#define LL 1024   // H*W
#define NHD 8
#define HD 64
#define WHALF 16  // WINDOW/2

// ---------------- scratch (static device globals; no runtime allocation) ----
__device__ float g_xwalze[BB*CC*HH*WW];          // (B,C,H,W) post-walze
__device__ __nv_bfloat16 g_comb[BB*LL*2*CC];     // (B*L, 2C): [before | after]
__device__ float g_mask[BB*LL];                  // soft mask
__device__ __nv_bfloat16 g_qkv[BB*LL*3*CC];      // (B*L, 3C) bf16, Q pre-scaled
__device__ __nv_bfloat16 g_ctx[BB*LL*CC];        // attention context (bf16)
__device__ __nv_bfloat16 g_ipw[3*CC*CC];         // bf16 in_proj_w
__device__ __nv_bfloat16 g_opw[CC*CC];           // bf16 out_proj_w
__device__ __nv_bfloat16 g_w1[128*2*CC];         // bf16 det_w1

__device__ __forceinline__ float gelu_exact(float v) {
    return 0.5f * v * (1.0f + erff(v * 0.70710678118654752440f));
}
__device__ __forceinline__ uint32_t smem_u32(const void* p) {
    uint32_t a;
    asm("{ .reg .u64 t; cvta.to.shared.u64 t, %1; cvt.u32.u64 %0, t; }"
        : "=r"(a) : "l"(p));
    return a;
}
__device__ __forceinline__ void cp16(uint32_t dst, const void* src) {
    asm volatile("cp.async.cg.shared.global [%0], [%1], 16;" :: "r"(dst), "l"(src));
}
__device__ __forceinline__ void ldmx4(uint32_t addr, uint32_t& r0, uint32_t& r1,
                                      uint32_t& r2, uint32_t& r3) {
    asm volatile("ldmatrix.sync.aligned.m8n8.x4.shared.b16 {%0,%1,%2,%3}, [%4];"
                 : "=r"(r0), "=r"(r1), "=r"(r2), "=r"(r3) : "r"(addr));
}
__device__ __forceinline__ void ldmx2(uint32_t addr, uint32_t& r0, uint32_t& r1) {
    asm volatile("ldmatrix.sync.aligned.m8n8.x2.shared.b16 {%0,%1}, [%2];"
                 : "=r"(r0), "=r"(r1) : "r"(addr));
}
__device__ __forceinline__ void mma16(float* c, uint32_t a0, uint32_t a1,
                                      uint32_t a2, uint32_t a3,
                                      uint32_t b0, uint32_t b1) {
    asm volatile("mma.sync.aligned.m16n8k16.row.col.f32.bf16.bf16.f32 "
                 "{%0,%1,%2,%3}, {%4,%5,%6,%7}, {%8,%9}, {%0,%1,%2,%3};"
                 : "+f"(c[0]), "+f"(c[1]), "+f"(c[2]), "+f"(c[3])
                 : "r"(a0), "r"(a1), "r"(a2), "r"(a3), "r"(b0), "r"(b1));
}
__device__ __forceinline__ uint32_t bf2pack(float a, float b) {
    __nv_bfloat162 t = __floats2bfloat162_rn(a, b);
    return *(uint32_t*)&t;
}
__device__ __forceinline__ void stcs4(float* p, float4 v) {
    asm volatile("st.global.cs.v4.f32 [%0], {%1,%2,%3,%4};"
                 :: "l"(p), "f"(v.x), "f"(v.y), "f"(v.z), "f"(v.w) : "memory");
}

// ====== bf16 mma.sync GEMM body (validated) =================================
// EPI: 1 = bf16 store with Q-column 0.125 scaling, 2 = detector head,
//      3 = fused gated combine (smem-staged coalesced, MLP-batched).
template<int EPI, int MT>
__device__ __forceinline__ void
gemm_body(int bm, int bn,
          const __nv_bfloat16* __restrict__ A, int lda,
          const __nv_bfloat16* __restrict__ Bm, int ldb,
          const float* __restrict__ bias,
          float* __restrict__ Cm, int ldc, int K,
          const float* __restrict__ aux1,   // EPI2: w2    EPI3: mask
          const float* __restrict__ aux2,   // EPI2: b2    EPI3: xwalze
          char* smem)
{
    constexpr int TM = MT * 32;
    constexpr int ABYTES = TM * 128;
    constexpr int BUFB = ABYTES + 16384;
    const uint32_t sb = smem_u32(smem);
    const int tid = threadIdx.x, lane = tid & 31, wid = tid >> 5;
    const int wm0 = (wid & 1) * (TM / 2), wn0 = (wid >> 1) * 32;

    const int ld_row = tid >> 3;
    const uint32_t st_off =
        (uint32_t)(ld_row * 128 + (((tid & 7) * 16) ^ ((ld_row & 7) << 4)));
    const __nv_bfloat16* Agb = A  + (size_t)(bm + ld_row) * lda + (tid & 7) * 8;
    const __nv_bfloat16* Bgb = Bm + (size_t)(bn + ld_row) * ldb + (tid & 7) * 8;

    auto load_tile = [&](int buf, int ch) {
        uint32_t da = sb + buf * BUFB + st_off;
        uint32_t db = da + ABYTES;
        const __nv_bfloat16* sa  = Agb + ch * 64;
        const __nv_bfloat16* sbp = Bgb + ch * 64;
#pragma unroll
        for (int p = 0; p < MT; p++)
            cp16(da + p * 4096, sa + (size_t)p * 32 * lda);
#pragma unroll
        for (int p = 0; p < 4; p++)
            cp16(db + p * 4096, sbp + (size_t)p * 32 * ldb);
        asm volatile("cp.async.commit_group;" ::: "memory");
    };

    const int arow  = wm0 + (lane & 15);
    const uint32_t akb = ((uint32_t)(lane >> 4)) << 4;
    const uint32_t aswz = (uint32_t)((arow & 7) << 4);
    const uint32_t a_rowbase = (uint32_t)(arow * 128);
    const int brow  = wn0 + ((lane >> 4) << 3) + (lane & 7);
    const uint32_t bkb = (uint32_t)(((lane >> 3) & 1) << 4);
    const uint32_t bswz = (uint32_t)((brow & 7) << 4);
    const uint32_t b_rowbase = (uint32_t)(ABYTES + brow * 128);

    float c[MT][4][4];
#pragma unroll
    for (int i = 0; i < MT; i++)
#pragma unroll
        for (int j = 0; j < 4; j++)
#pragma unroll
            for (int k = 0; k < 4; k++) c[i][j][k] = 0.0f;

    const int nch = K >> 6;
    load_tile(0, 0);
    load_tile(1, 1);

    for (int ch = 0; ch < nch; ch++) {
        const int buf = ch % 3;
        if (ch + 1 < nch) asm volatile("cp.async.wait_group 1;" ::: "memory");
        else              asm volatile("cp.async.wait_group 0;" ::: "memory");
        __syncthreads();
        if (ch + 2 < nch) load_tile((ch + 2) % 3, ch + 2);

        const uint32_t base = sb + buf * BUFB;
#pragma unroll
        for (int ks = 0; ks < 4; ks++) {
            const uint32_t kso = (uint32_t)(ks * 32);
            uint32_t a[MT][4];
#pragma unroll
            for (int mt = 0; mt < MT; mt++)
                ldmx4(base + a_rowbase + (uint32_t)(mt * 2048) + ((kso + akb) ^ aswz),
                      a[mt][0], a[mt][1], a[mt][2], a[mt][3]);
            uint32_t b[4][2];
#pragma unroll
            for (int nt2 = 0; nt2 < 2; nt2++)
                ldmx4(base + b_rowbase + (uint32_t)(nt2 * 2048) + ((kso + bkb) ^ bswz),
                      b[nt2*2][0], b[nt2*2][1], b[nt2*2+1][0], b[nt2*2+1][1]);
#pragma unroll
            for (int mt = 0; mt < MT; mt++)
#pragma unroll
                for (int nt = 0; nt < 4; nt++)
                    mma16(c[mt][nt], a[mt][0], a[mt][1], a[mt][2], a[mt][3],
                          b[nt][0], b[nt][1]);
        }
    }

    if (EPI == 1) {
        __nv_bfloat16* Cb = (__nv_bfloat16*)Cm;
#pragma unroll
        for (int mt = 0; mt < MT; mt++) {
            const int r0 = bm + wm0 + mt * 16 + (lane >> 2);
#pragma unroll
            for (int nt = 0; nt < 4; nt++) {
                const int col = bn + wn0 + nt * 8 + (lane & 3) * 2;
                float2 bs = *(const float2*)(bias + col);
                float sc = (col < 512) ? 0.125f : 1.0f;
                float v0 = (c[mt][nt][0] + bs.x) * sc;
                float v1 = (c[mt][nt][1] + bs.y) * sc;
                float v2 = (c[mt][nt][2] + bs.x) * sc;
                float v3 = (c[mt][nt][3] + bs.y) * sc;
                *(uint32_t*)(Cb + (size_t)r0 * ldc + col)       = bf2pack(v0, v1);
                *(uint32_t*)(Cb + (size_t)(r0 + 8) * ldc + col) = bf2pack(v2, v3);
            }
        }
        return;
    }

    if (EPI == 2) {
        float* red = (float*)smem;
        __syncthreads();
        if (tid < TM) red[tid] = 0.0f;
        __syncthreads();
#pragma unroll
        for (int mt = 0; mt < MT; mt++) {
            float pA = 0.0f, pB = 0.0f;
#pragma unroll
            for (int nt = 0; nt < 4; nt++) {
                int col = bn + wn0 + nt * 8 + (lane & 3) * 2;
                float2 bs = *(const float2*)(bias + col);
                float w0 = aux1[col], w1 = aux1[col + 1];
                pA += gelu_exact(c[mt][nt][0] + bs.x) * w0
                    + gelu_exact(c[mt][nt][1] + bs.y) * w1;
                pB += gelu_exact(c[mt][nt][2] + bs.x) * w0
                    + gelu_exact(c[mt][nt][3] + bs.y) * w1;
            }
            pA += __shfl_xor_sync(0xffffffffu, pA, 1);
            pA += __shfl_xor_sync(0xffffffffu, pA, 2);
            pB += __shfl_xor_sync(0xffffffffu, pB, 1);
            pB += __shfl_xor_sync(0xffffffffu, pB, 2);
            if ((lane & 3) == 0) {
                int rA = wm0 + mt * 16 + (lane >> 2);
                atomicAdd(&red[rA], pA);
                atomicAdd(&red[rA + 8], pB);
            }
        }
        __syncthreads();
        if (tid < TM)
            Cm[bm + tid] = 1.0f / (1.0f + __expf(-(red[tid] + aux2[0])));
        return;
    }

    if (EPI == 3) {
        float* stage = (float*)smem;
        __syncthreads();
#pragma unroll
        for (int mt = 0; mt < MT; mt++) {
            const int row = wm0 + mt * 16 + (lane >> 2);
#pragma unroll
            for (int nt = 0; nt < 4; nt++) {
                const int col = wn0 + nt * 8 + (lane & 3) * 2;
                float2 bs = *(const float2*)(bias + bn + col);
                stage[col*136 + row]           = c[mt][nt][0] + bs.x;
                stage[(col+1)*136 + row]       = c[mt][nt][1] + bs.y;
                stage[col*136 + row + 8]       = c[mt][nt][2] + bs.x;
                stage[(col+1)*136 + row + 8]   = c[mt][nt][3] + bs.y;
            }
        }
        __syncthreads();
        const int bloc = bm >> 10, l0 = bm & (LL - 1);
        float4 mk = *(const float4*)(aux1 + bm + lane * 4);
        // MLP-batched: 4 xwalze LDGs in flight per group; streaming stores.
#pragma unroll
        for (int g = 0; g < 4; g++) {
            size_t oo[4];
            float4 xw[4];
#pragma unroll
            for (int j = 0; j < 4; j++) {
                int cr = wid + (g * 4 + j) * 8;
                oo[j] = ((size_t)(bloc*CC + bn + cr)) * LL + l0 + lane*4;
                xw[j] = *(const float4*)(aux2 + oo[j]);
            }
#pragma unroll
            for (int j = 0; j < 4; j++) {
                int cr = wid + (g * 4 + j) * 8;
                float4 vv = *(const float4*)&stage[cr*136 + lane*4];
                float4 r;
                r.x = xw[j].x + mk.x * vv.x;
                r.y = xw[j].y + mk.y * vv.y;
                r.z = xw[j].z + mk.z * vv.z;
                r.w = xw[j].w + mk.w * vv.w;
                stcs4(Cm + oo[j], r);
            }
        }
        return;
    }
}

// ---- fused launch: QKV GEMM (768 CTAs, MT=4) + detector (128 CTAs) ---------
#define QKV_BLOCKS 768
#define FUSED_SMEM (3 * (128*128 + 16384))   // 98304
__global__ void __launch_bounds__(256, 2)
fused_qkv_det(const __nv_bfloat16* __restrict__ comb,
              const __nv_bfloat16* __restrict__ ipw,
              const float* __restrict__ ipb,
              __nv_bfloat16* __restrict__ qkv,
              const __nv_bfloat16* __restrict__ w1,
              const float* __restrict__ det_b1,
              const float* __restrict__ det_w2,
              const float* __restrict__ det_b2,
              float* __restrict__ mask)
{
    extern __shared__ char smem[];
    int bx = blockIdx.x;
    if (bx < QKV_BLOCKS) {
        int bn = (bx % 12) * 128;
        int bm = (bx / 12) * 128;
        gemm_body<1,4>(bm, bn, comb + CC, 2*CC, ipw, CC, ipb,
                       (float*)qkv, 3*CC, CC, nullptr, nullptr, smem);
    } else {
        int bm = (bx - QKV_BLOCKS) * 64;
        gemm_body<2,2>(bm, 0, comb, 2*CC, w1, 2*CC, det_b1,
                       mask, 1, 2*CC, det_w2, det_b2, smem);
    }
}

// ---- out_proj GEMM fused with gated residual combine ------------------------
__global__ void __launch_bounds__(256, 2)
outproj_combine(const __nv_bfloat16* __restrict__ ctx,
                const __nv_bfloat16* __restrict__ opw,
                const float* __restrict__ opb,
                float* __restrict__ out,
                const float* __restrict__ mask,
                const float* __restrict__ xwalze)
{
    extern __shared__ char smem[];
    gemm_body<3,4>(blockIdx.y * 128, blockIdx.x * 128, ctx, CC, opw, CC,
                   opb, out, 0, CC, mask, xwalze, smem);
}

// ==== fused walze: full-plane conv/BN/GELU + comb pack + xwalze, 1 launch ====
// WCH=8 channels per block (512 plane blocks): better wave balance / occupancy.
// Tail blocks round the GEMM weights to bf16.
#define WCH 8
#define WPAD 1028
#define WALZE_PLANES 512                            // 8 b x 64 ct
#define RW_TOTAL (3*CC*CC + CC*CC + 128*2*CC)       // 1,179,648
#define RW_BLOCKS ((RW_TOTAL + 255)/256)            // 4608
#define WALZE_SMEM ((WCH*WPAD + WCH*136) * 4)       // 37248 B

__global__ void __launch_bounds__(256)
walze_fused(const float* __restrict__ x,
            const float* __restrict__ dw_w,
            const float* __restrict__ dw_b,
            const float* __restrict__ sh_w,
            const float* __restrict__ sh_b,
            const float* __restrict__ mixw,
            const float* __restrict__ gamma,
            const float* __restrict__ beta,
            const float* __restrict__ ipw,
            const float* __restrict__ opw,
            const float* __restrict__ w1)
{
    int bi = blockIdx.x;
    int tid = threadIdx.x;
    if (bi >= WALZE_PLANES) {
        int i = (bi - WALZE_PLANES) * 256 + tid;
        const int N1 = 3*CC*CC, N2 = CC*CC, N3 = 128*2*CC;
        if (i < N1)                 g_ipw[i] = __float2bfloat16_rn(ipw[i]);
        else if (i < N1 + N2)       g_opw[i - N1] = __float2bfloat16_rn(opw[i - N1]);
        else if (i < N1 + N2 + N3)  g_w1[i - N1 - N2] = __float2bfloat16_rn(w1[i - N1 - N2]);
        return;
    }
    extern __shared__ float sx[];            // [WCH][WPAD]
    float* swo = sx + WCH * WPAD;            // [WCH][136]

    int ct = bi & 63, b = bi >> 6;
    int c0 = ct * WCH;

    // load 8 x 1024 plane, float4 coalesced
    for (int i = tid; i < WCH * 256; i += 256) {
        int c = i >> 8, l4 = (i & 255) * 4;
        float4 v = *(const float4*)(x + ((size_t)(b*CC + c0 + c)) * LL + l4);
        *(float4*)(sx + c * WPAD + l4) = v;
    }
    __syncthreads();

    const int c = tid & 7;
    const int lb = tid >> 3;                 // 0..31
    const float* dk = dw_w + (c0 + c) * 9;
    float d0 = dk[0], d1 = dk[1], d2 = dk[2], d3 = dk[3], d4 = dk[4],
          d5 = dk[5], d6 = dk[6], d7 = dk[7], d8 = dk[8];
    float dwb = dw_b[c0 + c];
    float gm = gamma[c0 + c] * rsqrtf(1.0f + 1e-5f);
    float bt = beta[c0 + c];
    float s0 = sh_w[0], s1 = sh_w[1], s2 = sh_w[2], s3 = sh_w[3], s4 = sh_w[4],
          s5 = sh_w[5], s6 = sh_w[6], s7 = sh_w[7], s8 = sh_w[8];
    float shb = sh_b[0];
    float mix = 1.0f / (1.0f + __expf(-mixw[0]));
    const float* row = sx + c * WPAD;

    for (int k = 0; k < 8; k++) {
#pragma unroll
        for (int j = 0; j < 4; j++) {
            int ll = lb + 32 * j;            // 0..127 within slab
            int l = k * 128 + ll;
            int h = l >> 5, w = l & 31;
            int hm = (h + 31) & 31, hp = (h + 1) & 31;
            int wm = (w + 31) & 31, wp = (w + 1) & 31;
            float v00 = row[hm*32+wm], v01 = row[hm*32+w], v02 = row[hm*32+wp];
            float v10 = row[h*32+wm],  v11 = row[h*32+w],  v12 = row[h*32+wp];
            float v20 = row[hp*32+wm], v21 = row[hp*32+w], v22 = row[hp*32+wp];
            float mo = v00*d0 + v01*d1 + v02*d2 + v10*d3 + v11*d4 + v12*d5
                     + v20*d6 + v21*d7 + v22*d8 + dwb;
            float ex = v00*s0 + v01*s1 + v02*s2 + v10*s3 + v11*s4 + v12*s5
                     + v20*s6 + v21*s7 + v22*s8 + shb;
            float xw = gelu_exact(gm * (mix*mo + (1.0f-mix)*ex + v11) + bt);
            size_t dst = ((size_t)(b*LL + l)) * (2*CC) + c0 + c;
            g_comb[dst]      = __float2bfloat16_rn(v11);
            g_comb[dst + CC] = __float2bfloat16_rn(xw);
            swo[c * 136 + ll] = xw;
        }
        __syncthreads();
        // coalesced xwalze store for this slab (8 ch x 128 l = 1024 vals)
#pragma unroll
        for (int j = 0; j < 4; j++) {
            int idx = tid + 256 * j;         // 0..1023
            int c2 = idx >> 7, l2 = idx & 127;
            g_xwalze[((size_t)(b*CC + c0 + c2)) * LL + k*128 + l2] =
                swo[c2 * 136 + l2];
        }
        __syncthreads();
    }
}

// ============ banded attention via mma: S = QK^T, ctx = P V =================
#define ATT_VT  0                        // 64 x 208
#define ATT_LS  (ATT_VT + 64*208)        // 13312, 64 floats
#define ATT_Q   (ATT_LS + 256)           // 13568, 64 x 144
#define ATT_K   (ATT_Q + 64*144)         // 22784, 96 x 144
#define ATT_P   ATT_Q                    // aliases Q/K (needs 64*208 <= 23040)
#define ATT_SMEM (ATT_K + 96*144)        // 36608

__global__ void __launch_bounds__(256)
attn_kernel()
{
    extern __shared__ char smem[];
    const uint32_t sb = smem_u32(smem);
    int bi = blockIdx.x;
    int qt = bi & 15, h = (bi >> 4) & 7, b = bi >> 7;
    int q0 = qt * 64;
    int jlo = max(0, q0 - WHALF);
    int jhi = min(LL - 1, q0 + 63 + WHALF);
    int nrows = jhi - jlo + 1;              // 80 or 96
    int tid = threadIdx.x, lane = tid & 31, wid = tid >> 5;

    const __nv_bfloat16* qb = g_qkv + (size_t)(b*LL + q0) * (3*CC) + h*HD;
    for (int i = tid; i < 64*8; i += 256) {
        int r = i >> 3, cb = (i & 7) * 16;
        uint4 v = *(const uint4*)((const char*)(qb + (size_t)r * (3*CC)) + cb);
        *(uint4*)(smem + ATT_Q + r*144 + cb) = v;
    }
    const __nv_bfloat16* kb = g_qkv + (size_t)(b*LL + jlo) * (3*CC) + CC + h*HD;
    for (int i = tid; i < 96*8; i += 256) {
        int r = i >> 3, cb = (i & 7) * 16;
        uint4 v = make_uint4(0u, 0u, 0u, 0u);
        if (r < nrows)
            v = *(const uint4*)((const char*)(kb + (size_t)r * (3*CC)) + cb);
        *(uint4*)(smem + ATT_K + r*144 + cb) = v;
    }
    const __nv_bfloat16* vb = kb + CC;
    for (int i = tid; i < 96*16; i += 256) {
        int r = i >> 4, c4 = (i & 15) * 4;
        uint2 v = make_uint2(0u, 0u);
        if (r < nrows)
            v = *(const uint2*)(vb + (size_t)r * (3*CC) + c4);
        const __nv_bfloat16* hv = (const __nv_bfloat16*)&v;
        *(__nv_bfloat16*)(smem + ATT_VT + (c4+0)*208 + r*2) = hv[0];
        *(__nv_bfloat16*)(smem + ATT_VT + (c4+1)*208 + r*2) = hv[1];
        *(__nv_bfloat16*)(smem + ATT_VT + (c4+2)*208 + r*2) = hv[2];
        *(__nv_bfloat16*)(smem + ATT_VT + (c4+3)*208 + r*2) = hv[3];
    }
    if (tid < 64) ((float*)(smem + ATT_LS))[tid] = 0.0f;
    __syncthreads();

    const int wm0 = (wid & 1) * 32;
    const int wn0s = (wid >> 1) * 24;
    float s[2][3][4];
#pragma unroll
    for (int i = 0; i < 2; i++)
#pragma unroll
        for (int j = 0; j < 3; j++)
#pragma unroll
            for (int k = 0; k < 4; k++) s[i][j][k] = 0.0f;
    {
        const uint32_t aAddr = sb + ATT_Q + (uint32_t)((wm0 + (lane & 15)) * 144)
                             + ((uint32_t)(lane >> 4) << 4);
        const uint32_t bAddr4 = sb + ATT_K
                             + (uint32_t)((wn0s + ((lane >> 4) << 3) + (lane & 7)) * 144)
                             + (uint32_t)(((lane >> 3) & 1) << 4);
        const uint32_t bAddr2 = sb + ATT_K
                             + (uint32_t)((wn0s + 16 + (lane & 7)) * 144)
                             + (uint32_t)(((lane >> 3) & 1) << 4);
#pragma unroll
        for (int ks = 0; ks < 4; ks++) {
            const uint32_t kso = (uint32_t)(ks * 32);
            uint32_t a0[4], a1[4], bb[3][2];
            ldmx4(aAddr + kso,            a0[0], a0[1], a0[2], a0[3]);
            ldmx4(aAddr + 16*144 + kso,   a1[0], a1[1], a1[2], a1[3]);
            ldmx4(bAddr4 + kso, bb[0][0], bb[0][1], bb[1][0], bb[1][1]);
            ldmx2(bAddr2 + kso, bb[2][0], bb[2][1]);
#pragma unroll
            for (int nt = 0; nt < 3; nt++) {
                mma16(s[0][nt], a0[0], a0[1], a0[2], a0[3], bb[nt][0], bb[nt][1]);
                mma16(s[1][nt], a1[0], a1[1], a1[2], a1[3], bb[nt][0], bb[nt][1]);
            }
        }
    }
    __syncthreads();   // Q/K reads complete before P overwrites that region

    float* lsum = (float*)(smem + ATT_LS);
#pragma unroll
    for (int mt = 0; mt < 2; mt++) {
        int row = wm0 + mt * 16 + (lane >> 2);
        int qA = q0 + row, qB = qA + 8;
        float rs0 = 0.0f, rs1 = 0.0f;
#pragma unroll
        for (int nt = 0; nt < 3; nt++) {
            int col = wn0s + nt * 8 + (lane & 3) * 2;
            int gj0 = jlo + col, gj1 = gj0 + 1;
            bool a00 = (gj0 >= qA - WHALF) && (gj0 <= qA + WHALF) && (gj0 < LL);
            bool a01 = (gj1 >= qA - WHALF) && (gj1 <= qA + WHALF) && (gj1 < LL);
            bool a10 = (gj0 >= qB - WHALF) && (gj0 <= qB + WHALF) && (gj0 < LL);
            bool a11 = (gj1 >= qB - WHALF) && (gj1 <= qB + WHALF) && (gj1 < LL);
            float p00 = a00 ? __expf(s[mt][nt][0]) : 0.0f;
            float p01 = a01 ? __expf(s[mt][nt][1]) : 0.0f;
            float p10 = a10 ? __expf(s[mt][nt][2]) : 0.0f;
            float p11 = a11 ? __expf(s[mt][nt][3]) : 0.0f;
            rs0 += p00 + p01; rs1 += p10 + p11;
            *(uint32_t*)(smem + ATT_P + row*208 + col*2)     = bf2pack(p00, p01);
            *(uint32_t*)(smem + ATT_P + (row+8)*208 + col*2) = bf2pack(p10, p11);
        }
        rs0 += __shfl_xor_sync(0xffffffffu, rs0, 1);
        rs0 += __shfl_xor_sync(0xffffffffu, rs0, 2);
        rs1 += __shfl_xor_sync(0xffffffffu, rs1, 1);
        rs1 += __shfl_xor_sync(0xffffffffu, rs1, 2);
        if ((lane & 3) == 0) {
            atomicAdd(&lsum[row], rs0);
            atomicAdd(&lsum[row + 8], rs1);
        }
    }
    __syncthreads();

    const int wn0v = (wid >> 1) * 16;
    float o[2][2][4];
#pragma unroll
    for (int i = 0; i < 2; i++)
#pragma unroll
        for (int j = 0; j < 2; j++)
#pragma unroll
            for (int k = 0; k < 4; k++) o[i][j][k] = 0.0f;
    {
        const uint32_t aAddr = sb + ATT_P + (uint32_t)((wm0 + (lane & 15)) * 208)
                             + ((uint32_t)(lane >> 4) << 4);
        const uint32_t bAddr = sb + ATT_VT
                             + (uint32_t)((wn0v + ((lane >> 4) << 3) + (lane & 7)) * 208)
                             + (uint32_t)(((lane >> 3) & 1) << 4);
#pragma unroll
        for (int ks = 0; ks < 6; ks++) {
            const uint32_t kso = (uint32_t)(ks * 32);
            uint32_t a0[4], a1[4], bb[2][2];
            ldmx4(aAddr + kso,          a0[0], a0[1], a0[2], a0[3]);
            ldmx4(aAddr + 16*208 + kso, a1[0], a1[1], a1[2], a1[3]);
            ldmx4(bAddr + kso, bb[0][0], bb[0][1], bb[1][0], bb[1][1]);
#pragma unroll
            for (int nt = 0; nt < 2; nt++) {
                mma16(o[0][nt], a0[0], a0[1], a0[2], a0[3], bb[nt][0], bb[nt][1]);
                mma16(o[1][nt], a1[0], a1[1], a1[2], a1[3], bb[nt][0], bb[nt][1]);
            }
        }
    }

#pragma unroll
    for (int mt = 0; mt < 2; mt++) {
        int row = wm0 + mt * 16 + (lane >> 2);
        float inv0 = 1.0f / lsum[row];
        float inv1 = 1.0f / lsum[row + 8];
#pragma unroll
        for (int nt = 0; nt < 2; nt++) {
            int col = wn0v + nt * 8 + (lane & 3) * 2;
            __nv_bfloat16* d0 = g_ctx + (size_t)(b*LL + q0 + row) * CC + h*HD + col;
            __nv_bfloat16* d1 = d0 + (size_t)8 * CC;
            *(uint32_t*)d0 = bf2pack(o[mt][nt][0] * inv0, o[mt][nt][1] * inv0);
            *(uint32_t*)d1 = bf2pack(o[mt][nt][2] * inv1, o[mt][nt][3] * inv1);
        }
    }
}

// ---------------- host launcher ---------------------------------------------
extern "C" void kernel_launch(void* const* d_in, const int* in_sizes, int n_in,
                              void* d_out, int out_size)
{
    const float* x      = (const float*)d_in[0];
    const float* dw_w   = (const float*)d_in[1];
    const float* dw_b   = (const float*)d_in[2];
    const float* sh_w   = (const float*)d_in[3];
    const float* sh_b   = (const float*)d_in[4];
    const float* mixw   = (const float*)d_in[5];
    const float* gamma  = (const float*)d_in[6];
    const float* beta   = (const float*)d_in[7];
    const float* det_w1 = (const float*)d_in[8];
    const float* det_b1 = (const float*)d_in[9];
    const float* det_w2 = (const float*)d_in[10];
    const float* det_b2 = (const float*)d_in[11];
    const float* ipw    = (const float*)d_in[12];
    const float* ipb    = (const float*)d_in[13];
    const float* opw    = (const float*)d_in[14];
    const float* opb    = (const float*)d_in[15];
    float* out = (float*)d_out;

    __nv_bfloat16 *p_comb, *p_ctx, *p_ipw, *p_opw, *p_w1, *p_qkv;
    float *p_mask, *p_xwalze;
    cudaGetSymbolAddress((void**)&p_comb,    g_comb);
    cudaGetSymbolAddress((void**)&p_qkv,     g_qkv);
    cudaGetSymbolAddress((void**)&p_ctx,     g_ctx);
    cudaGetSymbolAddress((void**)&p_ipw,     g_ipw);
    cudaGetSymbolAddress((void**)&p_opw,     g_opw);
    cudaGetSymbolAddress((void**)&p_w1,      g_w1);
    cudaGetSymbolAddress((void**)&p_mask,    g_mask);
    cudaGetSymbolAddress((void**)&p_xwalze,  g_xwalze);

    cudaFuncSetAttribute((const void*)fused_qkv_det,
                         cudaFuncAttributeMaxDynamicSharedMemorySize, FUSED_SMEM);
    cudaFuncSetAttribute((const void*)outproj_combine,
                         cudaFuncAttributeMaxDynamicSharedMemorySize, FUSED_SMEM);
    cudaFuncSetAttribute((const void*)attn_kernel,
                         cudaFuncAttributeMaxDynamicSharedMemorySize, ATT_SMEM);
    cudaFuncSetAttribute((const void*)walze_fused,
                         cudaFuncAttributeMaxDynamicSharedMemorySize, WALZE_SMEM);

    // 1) fused walze: conv/BN/GELU + comb pack + xwalze (+ weight rounding tail)
    walze_fused<<<WALZE_PLANES + RW_BLOCKS, 256, WALZE_SMEM>>>(
        x, dw_w, dw_b, sh_w, sh_b, mixw, gamma, beta, ipw, opw, det_w1);

    // 2) fused QKV GEMM (bf16 out, Q pre-scaled) + detector GEMM/head
    fused_qkv_det<<<QKV_BLOCKS + 128, 256, FUSED_SMEM>>>(
        p_comb, p_ipw, ipb, p_qkv, p_w1, det_b1, det_w2, det_b2, p_mask);

    // 3) banded attention (mma-based, bf16 I/O)
    attn_kernel<<<BB*NHD*(LL/64), 256, ATT_SMEM>>>();

    // 4) out_proj GEMM fused with gated residual combine -> out
    {
        dim3 g(CC/128, (BB*LL)/128);
        outproj_combine<<<g, 256, FUSED_SMEM>>>(p_ctx, p_opw, opb, out,
                                                p_mask, p_xwalze);
    }
}